// round 14
// baseline (speedup 1.0000x reference)
#include <cuda_runtime.h>
#include <math.h>

#define BB 32
#define SS 256
#define EE 300
#define EP 304
#define HH 256
#define T4H 1024
#define NT 19
#define TSTART 17
#define TSTOP 18

typedef unsigned long long ull;

__device__ __forceinline__ ull fma2(ull a, ull b, ull c) {
    ull d;
    asm("fma.rn.f32x2 %0, %1, %2, %3;" : "=l"(d) : "l"(a), "l"(b), "l"(c));
    return d;
}
__device__ __forceinline__ ull pack2(float lo, float hi) {
    ull r;
    asm("mov.b64 %0, {%1, %2};" : "=l"(r) : "f"(lo), "f"(hi));
    return r;
}
__device__ __forceinline__ float fsigmoid(float x) {
    return 1.0f / (1.0f + __expf(-x));
}
__device__ __forceinline__ float ftanh_fast(float x) {
    return 1.0f - 2.0f / (__expf(2.0f * x) + 1.0f);
}
#define BAR1_128() asm volatile("bar.sync 1, 128;" ::: "memory")

// ---------------- device scratch (no cudaMalloc allowed) ----------------
__device__ float    g_X[(size_t)BB * SS * EP];            // [n][e], n = t*32 + b
__device__ float    g_xg[(size_t)2 * SS * T4H * BB];      // [d][t][row][b]
__device__ float    g_h[(size_t)2 * SS * HH * BB];        // [d][t][k][b]
__device__ float    g_logits[(size_t)BB * SS * NT];       // [b][t*NT+tag]
__device__ unsigned g_bar[2 * SS * 4];                    // lstm [dir][step][group] counters
__device__ unsigned g_xgready[2 * 64];                    // [dir][chunk(4 steps)] counters

// ---------------- embedding gather + mask -> padded X; inits out[0] + all counters ----------------
__global__ void embed_kernel(const int* __restrict__ word, const int* __restrict__ mask,
                             const float* __restrict__ emb, float* __restrict__ out) {
    int idx = blockIdx.x * blockDim.x + threadIdx.x;
    if (idx == 0) out[0] = 0.0f;
    if (idx < 2 * SS * 4) g_bar[idx] = 0u;
    if (idx < 2 * 64) g_xgready[idx] = 0u;
    int total = BB * SS * (EP / 4);
    if (idx >= total) return;
    int n = idx / (EP / 4), q = idx - n * (EP / 4);
    int t = n >> 5, b = n & 31;
    int w = word[b * SS + t];
    float m = (float)mask[b * SS + t];
    int e = q * 4;
    float4 v;
    if (e < EE) {
        float4 ev = *(const float4*)(emb + (size_t)w * EE + e);
        v.x = ev.x * m; v.y = ev.y * m; v.z = ev.z * m; v.w = ev.w * m;
    } else {
        v.x = v.y = v.z = v.w = 0.0f;
    }
    ((float4*)g_X)[(size_t)n * (EP / 4) + q] = v;
}

// ---------------- fused kernel: 128 lstm-role blocks + 2048 gemm-role blocks ----------------
// gemm role g = bid-128: rowblk = g&15 (m0 = rowblk*64); yy = g>>4; dd = yy&1;
// chunk = dd ? 63-(yy>>1) : (yy>>1); n0 = chunk*128 tokens (timesteps 4c..4c+3, all 32 b).
// Publishes red.release into g_xgready[dd*64+chunk] (target 16).
// lstm role: round-5 recurrence; gates each new 4-step chunk on g_xgready.
__global__ __launch_bounds__(256, 2) void fused_kernel(
    const float* __restrict__ WihF, const float* __restrict__ WihB,
    const float* __restrict__ bihF, const float* __restrict__ bhhF,
    const float* __restrict__ bihB, const float* __restrict__ bhhB,
    const float* __restrict__ WhhF, const float* __restrict__ WhhB) {
    extern __shared__ ull sm8[];
    int tid = threadIdx.x, bid = blockIdx.x;

    if (bid >= 128) {
        // ================= GEMM role =================
        ull*   As = sm8;                         // [2][16][64] ull
        float* Xs = (float*)(sm8 + 2048);        // [2][16][132] float
        int g = bid - 128;
        int m0 = (g & 15) * 64;
        int yy = g >> 4;
        int dd = yy & 1;
        int chunk = dd ? (63 - (yy >> 1)) : (yy >> 1);
        int n0 = chunk * 128;
        const float* Wih = dd ? WihB : WihF;
        const float* bih = dd ? bihB : bihF;
        const float* bhh = dd ? bhhB : bhhF;
        int lmA = tid >> 2, kqA = (tid & 3) * 4;
        int tok = tid >> 1, f4b = (tid & 1) * 2;
        int tx = tid & 15, ty = tid >> 4;
        #define ASB(bf, k, r) As[(size_t)(bf) * 1024 + (k) * 64 + (r)]
        #define XSB(bf, k, c) Xs[(size_t)(bf) * 2112 + (k) * 132 + (c)]

        ull acc[4][4];
#pragma unroll
        for (int i = 0; i < 4; i++)
#pragma unroll
            for (int j = 0; j < 4; j++) acc[i][j] = 0ULL;

        float4 wv, xv0, xv1;
        if (kqA < EE) wv = *(const float4*)(Wih + (size_t)(m0 + lmA) * EE + kqA);
        else { wv.x = wv.y = wv.z = wv.w = 0.0f; }
        xv0 = *(const float4*)(g_X + (size_t)(n0 + tok) * EP + f4b * 4);
        xv1 = *(const float4*)(g_X + (size_t)(n0 + tok) * EP + f4b * 4 + 4);
        ASB(0, kqA + 0, lmA) = pack2(wv.x, wv.x);
        ASB(0, kqA + 1, lmA) = pack2(wv.y, wv.y);
        ASB(0, kqA + 2, lmA) = pack2(wv.z, wv.z);
        ASB(0, kqA + 3, lmA) = pack2(wv.w, wv.w);
        XSB(0, f4b * 4 + 0, tok) = xv0.x; XSB(0, f4b * 4 + 1, tok) = xv0.y;
        XSB(0, f4b * 4 + 2, tok) = xv0.z; XSB(0, f4b * 4 + 3, tok) = xv0.w;
        XSB(0, f4b * 4 + 4, tok) = xv1.x; XSB(0, f4b * 4 + 5, tok) = xv1.y;
        XSB(0, f4b * 4 + 6, tok) = xv1.z; XSB(0, f4b * 4 + 7, tok) = xv1.w;
        __syncthreads();

        const int NTILE = EP / 16;  // 19
        for (int i = 0; i < NTILE; i++) {
            int cb = i & 1, nb = (i + 1) & 1;
            if (i + 1 < NTILE) {
                int e0 = (i + 1) * 16;
                if (e0 + kqA < EE) wv = *(const float4*)(Wih + (size_t)(m0 + lmA) * EE + e0 + kqA);
                else { wv.x = wv.y = wv.z = wv.w = 0.0f; }
                xv0 = *(const float4*)(g_X + (size_t)(n0 + tok) * EP + e0 + f4b * 4);
                xv1 = *(const float4*)(g_X + (size_t)(n0 + tok) * EP + e0 + f4b * 4 + 4);
            }
#pragma unroll
            for (int k = 0; k < 16; k++) {
                ulonglong2 wA = *(const ulonglong2*)&ASB(cb, k, ty * 2);
                ulonglong2 wB = *(const ulonglong2*)&ASB(cb, k, 32 + ty * 2);
                ulonglong2 xA = *(const ulonglong2*)&XSB(cb, k, tx * 4);
                ulonglong2 xB = *(const ulonglong2*)&XSB(cb, k, 64 + tx * 4);
                acc[0][0] = fma2(wA.x, xA.x, acc[0][0]); acc[0][1] = fma2(wA.x, xA.y, acc[0][1]);
                acc[0][2] = fma2(wA.x, xB.x, acc[0][2]); acc[0][3] = fma2(wA.x, xB.y, acc[0][3]);
                acc[1][0] = fma2(wA.y, xA.x, acc[1][0]); acc[1][1] = fma2(wA.y, xA.y, acc[1][1]);
                acc[1][2] = fma2(wA.y, xB.x, acc[1][2]); acc[1][3] = fma2(wA.y, xB.y, acc[1][3]);
                acc[2][0] = fma2(wB.x, xA.x, acc[2][0]); acc[2][1] = fma2(wB.x, xA.y, acc[2][1]);
                acc[2][2] = fma2(wB.x, xB.x, acc[2][2]); acc[2][3] = fma2(wB.x, xB.y, acc[2][3]);
                acc[3][0] = fma2(wB.y, xA.x, acc[3][0]); acc[3][1] = fma2(wB.y, xA.y, acc[3][1]);
                acc[3][2] = fma2(wB.y, xB.x, acc[3][2]); acc[3][3] = fma2(wB.y, xB.y, acc[3][3]);
            }
            if (i + 1 < NTILE) {
                ASB(nb, kqA + 0, lmA) = pack2(wv.x, wv.x);
                ASB(nb, kqA + 1, lmA) = pack2(wv.y, wv.y);
                ASB(nb, kqA + 2, lmA) = pack2(wv.z, wv.z);
                ASB(nb, kqA + 3, lmA) = pack2(wv.w, wv.w);
                XSB(nb, f4b * 4 + 0, tok) = xv0.x; XSB(nb, f4b * 4 + 1, tok) = xv0.y;
                XSB(nb, f4b * 4 + 2, tok) = xv0.z; XSB(nb, f4b * 4 + 3, tok) = xv0.w;
                XSB(nb, f4b * 4 + 4, tok) = xv1.x; XSB(nb, f4b * 4 + 5, tok) = xv1.y;
                XSB(nb, f4b * 4 + 6, tok) = xv1.z; XSB(nb, f4b * 4 + 7, tok) = xv1.w;
            }
            __syncthreads();
        }

        int rows[4] = {m0 + ty * 2, m0 + ty * 2 + 1, m0 + 32 + ty * 2, m0 + 33 + ty * 2};
#pragma unroll
        for (int i = 0; i < 4; i++) {
            int row = rows[i];
            float bias = bih[row] + bhh[row];
#pragma unroll
            for (int c = 0; c < 4; c++) {
                float2 f = *(float2*)&acc[i][c];
                int n = n0 + (c < 2 ? tx * 4 + c * 2 : 64 + tx * 4 + (c - 2) * 2);
                int tt = n >> 5, bb2 = n & 31;
                float2 o;
                o.x = f.x + bias; o.y = f.y + bias;
                *(float2*)&g_xg[(((size_t)dd * SS + tt) * T4H + row) * BB + bb2] = o;
            }
        }
        __syncthreads();  // all 16 rowblock-threads' xg stores done before release
        if (tid == 0) {
            unsigned* fp = g_xgready + dd * 64 + chunk;
            asm volatile("red.release.gpu.global.add.u32 [%0], %1;" :: "l"(fp), "r"(1u) : "memory");
        }
        return;
    }

    // ================= LSTM role (round-5 recurrence + chunk gating) =================
    if (tid >= 128) return;  // warps 4-7 exit; all syncs below are named bar 1,128
    ull*   W_dup = sm8;
    float* h_s   = (float*)(sm8 + 4096);
    ull*   part  = sm8 + 8192;

    int d = bid >> 6, m = bid & 63;
    const float* Whh = d ? WhhB : WhhF;

    for (int i = tid; i < 4096; i += 128) {
        int r = i & 15, k = i >> 4;
        int gg = r >> 2, uu = r & 3;
        float w = Whh[(size_t)(gg * HH + m * 4 + uu) * HH + k];
        W_dup[k * 16 + r] = pack2(w, w);
    }
    BAR1_128();

    int lane = tid & 31, w = tid >> 5;
    int ggl = lane & 3, bg = lane >> 2;
    const ulonglong2* Wd2 = (const ulonglong2*)W_dup;
    const ulonglong2* H2  = (const ulonglong2*)h_s;
    int u = tid >> 5, b = tid & 31;
    float c_reg = 0.0f;
    unsigned* barD = g_bar + d * SS * 4;
    const unsigned* xgrD = g_xgready + d * 64;
    int mygrp = m >> 4;
    int last_ch = -1;

    for (int it = 0; it < SS; it++) {
        int t = d ? (SS - 1 - it) : it;

        // gate on this 4-step chunk's xg availability (16 gemm rowblocks)
        int ch = t >> 2;
        if (ch != last_ch) {
            const unsigned* fp = xgrD + ch;
            unsigned v;
            do {
                asm volatile("ld.acquire.gpu.global.u32 %0, [%1];" : "=r"(v) : "l"(fp) : "memory");
            } while (v < 16u);
            last_ch = ch;
        }

        float xgv[4];
        const float* xgb = g_xg + ((size_t)(d * SS + t) * T4H) * BB;
#pragma unroll
        for (int gg = 0; gg < 4; gg++)
            xgv[gg] = xgb[(size_t)(gg * HH + m * 4 + u) * BB + b];

        if (it > 0) {
            unsigned* cp = barD + (it - 1) * 4 + w;
            unsigned v;
            do {
                asm volatile("ld.acquire.gpu.global.u32 %0, [%1];" : "=r"(v) : "l"(cp) : "memory");
            } while (v < 16u);

            int tp = d ? t + 1 : t - 1;
            const float4* src4 = (const float4*)(g_h + (size_t)(d * SS + tp) * HH * BB);
            float4* dst4 = (float4*)h_s;
#pragma unroll
            for (int j = 0; j < 16; j++) {
                int idx = w * 512 + lane + j * 32;
                dst4[idx] = src4[idx];
            }
            __syncwarp();

            ull a[4][2];
#pragma unroll
            for (int i = 0; i < 4; i++) { a[i][0] = 0ULL; a[i][1] = 0ULL; }
            int k0 = w * 64;
#pragma unroll 8
            for (int k = k0; k < k0 + 64; k++) {
                ulonglong2 w01 = Wd2[k * 8 + ggl * 2];
                ulonglong2 w23 = Wd2[k * 8 + ggl * 2 + 1];
                ulonglong2 hh  = H2[k * 8 + bg];
                a[0][0] = fma2(w01.x, hh.x, a[0][0]); a[0][1] = fma2(w01.x, hh.y, a[0][1]);
                a[1][0] = fma2(w01.y, hh.x, a[1][0]); a[1][1] = fma2(w01.y, hh.y, a[1][1]);
                a[2][0] = fma2(w23.x, hh.x, a[2][0]); a[2][1] = fma2(w23.x, hh.y, a[2][1]);
                a[3][0] = fma2(w23.y, hh.x, a[3][0]); a[3][1] = fma2(w23.y, hh.y, a[3][1]);
            }
#pragma unroll
            for (int i = 0; i < 4; i++) {
                ull* pr = part + (size_t)(w * 16 + ggl * 4 + i) * 17 + bg * 2;
                pr[0] = a[i][0]; pr[1] = a[i][1];
            }
        }
        BAR1_128();

        {
            const float* pf = (const float*)part;
            float g[4];
#pragma unroll
            for (int gg = 0; gg < 4; gg++) {
                float s = xgv[gg];
                if (it > 0) {
                    int r = gg * 4 + u;
#pragma unroll
                    for (int wi = 0; wi < 4; wi++)
                        s += pf[(((size_t)wi * 16 + r) * 17 + (b >> 1)) * 2 + (b & 1)];
                }
                g[gg] = s;
            }
            float iv = fsigmoid(g[0]);
            float fv = fsigmoid(g[1]);
            float gv = ftanh_fast(g[2]);
            float ov = fsigmoid(g[3]);
            c_reg = fv * c_reg + iv * gv;
            g_h[((size_t)(d * SS + t) * HH + m * 4 + u) * BB + b] = ov * ftanh_fast(c_reg);
        }
        BAR1_128();

        if (tid == 0) {
            unsigned* ap = barD + it * 4 + mygrp;
            asm volatile("red.release.gpu.global.add.u32 [%0], %1;" :: "l"(ap), "r"(1u) : "memory");
        }
    }
}

// ---------------- logits: Wtag staged in smem ----------------
__global__ __launch_bounds__(256) void logits_kernel(const float* __restrict__ Wtag,
                                                     const float* __restrict__ btag) {
    extern __shared__ float hb[];
    float* wt = hb + 512 * 32;
    int t = blockIdx.x;
    int tid = threadIdx.x;
    for (int dd = 0; dd < 2; dd++) {
        const float4* src = (const float4*)(g_h + (size_t)(dd * SS + t) * HH * BB);
        float4* dst = (float4*)(hb + (size_t)dd * HH * BB);
        for (int i = tid; i < 2048; i += 256) dst[i] = src[i];
    }
    {
        const float4* ws = (const float4*)Wtag;
        float4* wd = (float4*)wt;
        for (int i = tid; i < 2432; i += 256) wd[i] = ws[i];
    }
    __syncthreads();
    for (int o = tid; o < BB * NT; o += 256) {
        int tag = o >> 5;
        int b = o & 31;
        float acc = btag[tag];
        const float* wr = wt + tag * 512;
#pragma unroll 8
        for (int k = 0; k < 2 * HH; k++) acc += hb[k * BB + b] * wr[k];
        g_logits[((size_t)b * SS + t) * NT + tag] = acc;
    }
}

// ---------------- merged CRF forward + Viterbi, fully smem-staged ----------------
__global__ void crf_vit_kernel(const int* __restrict__ mask, const int* __restrict__ labels,
                               const float* __restrict__ trans, float* __restrict__ out) {
    extern __shared__ float smc[];
    float* tr  = smc;
    float* lg  = smc + 364;
    int*   msk = (int*)(smc + 364 + 4864);
    int*   lbl = msk + 256;
    int*   ptr_s = msk + 512;
    __shared__ float st[NT];

    int b = blockIdx.x, j = threadIdx.x;
    for (int i = j; i < NT * NT; i += 32) tr[i] = trans[i];
    {
        const float4* src = (const float4*)(g_logits + (size_t)b * SS * NT);
        float4* dst = (float4*)lg;
        for (int i = j; i < SS * NT / 4; i += 32) dst[i] = src[i];
    }
    for (int i = j; i < SS; i += 32) {
        msk[i] = mask[b * SS + i];
        lbl[i] = labels[b * SS + i];
    }
    __syncthreads();

    if (blockIdx.y == 0) {
        if (j < NT) st[j] = lg[j] + tr[TSTART * NT + j];
        __syncthreads();
        for (int t = 1; t < SS; t++) {
            int mt = msk[t];
            float nv = 0.0f;
            if (j < NT) {
                float mx = -1e30f;
#pragma unroll
                for (int i = 0; i < NT; i++) mx = fmaxf(mx, st[i] + tr[i * NT + j]);
                float sum = 0.0f;
#pragma unroll
                for (int i = 0; i < NT; i++) sum += __expf(st[i] + tr[i * NT + j] - mx);
                nv = mx + __logf(sum) + lg[t * NT + j];
            }
            __syncthreads();
            if (j < NT && mt > 0) st[j] = nv;
            __syncthreads();
        }
        if (j == 0) {
            float mx = -1e30f;
            for (int i = 0; i < NT; i++) mx = fmaxf(mx, st[i] + tr[i * NT + TSTOP]);
            float sum = 0.0f;
            for (int i = 0; i < NT; i++) sum += __expf(st[i] + tr[i * NT + TSTOP] - mx);
            float logZ = mx + __logf(sum);
            float gold = 0.0f;
            int prev = TSTART, len = 0;
            for (int t = 0; t < SS; t++) {
                int lab = lbl[t];
                if (msk[t] > 0) {
                    gold += tr[prev * NT + lab] + lg[t * NT + lab];
                    len++;
                }
                prev = lab;
            }
            int last = lbl[len - 1];
            gold += tr[last * NT + TSTOP];
            atomicAdd(out, (logZ - gold) * (1.0f / (float)BB));
        }
    } else {
        if (j < NT) st[j] = lg[j] + tr[TSTART * NT + j];
        __syncthreads();
        for (int t = 1; t < SS; t++) {
            int mt = msk[t];
            float nv = 0.0f;
            int arg = j;
            if (j < NT) {
                float best = -1e30f;
                int bi = 0;
#pragma unroll
                for (int i = 0; i < NT; i++) {
                    float v = st[i] + tr[i * NT + j];
                    if (v > best) { best = v; bi = i; }
                }
                nv = best + lg[t * NT + j];
                if (mt > 0) arg = bi;
            }
            __syncthreads();
            if (j < NT) {
                if (mt > 0) st[j] = nv;
                ptr_s[t * NT + j] = arg;
            }
            __syncthreads();
        }
        if (j == 0) {
            float best = -1e30f;
            int bl = 0;
            for (int i = 0; i < NT; i++) {
                float v = st[i] + tr[i * NT + TSTOP];
                if (v > best) { best = v; bl = i; }
            }
            int tag = bl;
            for (int t = SS - 1; t >= 1; t--) {
                out[1 + b * SS + t] = (float)(msk[t] > 0 ? tag : 0);
                tag = ptr_s[t * NT + tag];
            }
            out[1 + b * SS + 0] = (float)(msk[0] > 0 ? tag : 0);
        }
    }
}

extern "C" void kernel_launch(void* const* d_in, const int* in_sizes, int n_in,
                              void* d_out, int out_size) {
    int o = (in_sizes[4] == 1) ? 0 : -1;
    const int*   word   = (const int*)d_in[0];
    const int*   mask   = (const int*)d_in[1];
    const int*   labels = (const int*)d_in[2];
    const float* emb    = (const float*)d_in[5 + o];
    const float* WihF   = (const float*)d_in[6 + o];
    const float* WhhF   = (const float*)d_in[7 + o];
    const float* bihF   = (const float*)d_in[8 + o];
    const float* bhhF   = (const float*)d_in[9 + o];
    const float* WihB   = (const float*)d_in[10 + o];
    const float* WhhB   = (const float*)d_in[11 + o];
    const float* bihB   = (const float*)d_in[12 + o];
    const float* bhhB   = (const float*)d_in[13 + o];
    const float* Wtag   = (const float*)d_in[14 + o];
    const float* btag   = (const float*)d_in[15 + o];
    const float* trans  = (const float*)d_in[16 + o];
    float* out = (float*)d_out;

    const int fused_smem = (4096 + 4096 + 1088) * 8;          // 74240 B (covers both roles)
    const int logits_smem = (512 * 32 + 19 * 512) * 4;        // 104448 B
    const int crf_smem = (364 + 4864 + 256 + 256 + 4864) * 4; // 42416 B
    cudaFuncSetAttribute(fused_kernel, cudaFuncAttributeMaxDynamicSharedMemorySize, fused_smem);
    cudaFuncSetAttribute(logits_kernel, cudaFuncAttributeMaxDynamicSharedMemorySize, logits_smem);

    embed_kernel<<<(BB * SS * (EP / 4) + 255) / 256, 256>>>(word, mask, emb, out);
    fused_kernel<<<128 + 2048, 256, fused_smem>>>(WihF, WihB, bihF, bhhF, bihB, bhhB,
                                                  WhhF, WhhB);
    logits_kernel<<<SS, 256, logits_smem>>>(Wtag, btag);
    crf_vit_kernel<<<dim3(BB, 2), 32, crf_smem>>>(mask, labels, trans, out);
}

// round 15
// speedup vs baseline: 1.0324x; 1.0324x over previous
#include <cuda_runtime.h>
#include <math.h>

#define BB 32
#define SS 256
#define EE 300
#define EP 304
#define HH 256
#define T4H 1024
#define NT 19
#define TSTART 17
#define TSTOP 18

typedef unsigned long long ull;

__device__ __forceinline__ ull fma2(ull a, ull b, ull c) {
    ull d;
    asm("fma.rn.f32x2 %0, %1, %2, %3;" : "=l"(d) : "l"(a), "l"(b), "l"(c));
    return d;
}
__device__ __forceinline__ ull pack2(float lo, float hi) {
    ull r;
    asm("mov.b64 %0, {%1, %2};" : "=l"(r) : "f"(lo), "f"(hi));
    return r;
}
__device__ __forceinline__ float fsigmoid(float x) {
    return 1.0f / (1.0f + __expf(-x));
}
__device__ __forceinline__ float ftanh_fast(float x) {
    return 1.0f - 2.0f / (__expf(2.0f * x) + 1.0f);
}

// ---------------- device scratch (no cudaMalloc allowed) ----------------
__device__ float    g_X[(size_t)BB * SS * EP];            // [n][e], n = t*32 + b
__device__ float    g_xg[(size_t)2 * SS * T4H * BB];      // [d][t][row][b]
__device__ float    g_h[(size_t)2 * SS * HH * BB];        // [d][t][k][b]
__device__ float    g_logits[(size_t)BB * SS * NT];       // [b][t*NT+tag]
__device__ unsigned g_bar[2 * SS * 4];                    // [dir][step][group] arrival counters

// ---------------- embedding gather + mask -> padded X; inits out[0] + counters ----------------
__global__ void embed_kernel(const int* __restrict__ word, const int* __restrict__ mask,
                             const float* __restrict__ emb, float* __restrict__ out) {
    int idx = blockIdx.x * blockDim.x + threadIdx.x;
    if (idx == 0) out[0] = 0.0f;
    if (idx < 2 * SS * 4) g_bar[idx] = 0u;
    int total = BB * SS * (EP / 4);
    if (idx >= total) return;
    int n = idx / (EP / 4), q = idx - n * (EP / 4);
    int t = n >> 5, b = n & 31;
    int w = word[b * SS + t];
    float m = (float)mask[b * SS + t];
    int e = q * 4;
    float4 v;
    if (e < EE) {
        float4 ev = *(const float4*)(emb + (size_t)w * EE + e);
        v.x = ev.x * m; v.y = ev.y * m; v.z = ev.z * m; v.w = ev.w * m;
    } else {
        v.x = v.y = v.z = v.w = 0.0f;
    }
    ((float4*)g_X)[(size_t)n * (EP / 4) + q] = v;
}

// ---------------- input-transform GEMM: double-buffered, conflict-free f32x2 (R13) ----------------
__global__ __launch_bounds__(256) void gemm_xg_kernel(
    const float* __restrict__ WihF, const float* __restrict__ WihB,
    const float* __restrict__ bihF, const float* __restrict__ bhhF,
    const float* __restrict__ bihB, const float* __restrict__ bhhB) {
    __shared__ ull   As[2][16][64];
    __shared__ float Xs[2][16][132];
    int d = blockIdx.z;
    const float* Wih = d ? WihB : WihF;
    const float* bih = d ? bihB : bihF;
    const float* bhh = d ? bhhB : bhhF;
    int m0 = blockIdx.y * 64, n0 = blockIdx.x * 128;
    int tid = threadIdx.x;
    int lmA = tid >> 2, kqA = (tid & 3) * 4;
    int tok = tid >> 1, f4b = (tid & 1) * 2;
    int tx = tid & 15, ty = tid >> 4;

    ull acc[4][4];
#pragma unroll
    for (int i = 0; i < 4; i++)
#pragma unroll
        for (int j = 0; j < 4; j++) acc[i][j] = 0ULL;

    float4 wv, xv0, xv1;
    {
        if (kqA < EE) wv = *(const float4*)(Wih + (size_t)(m0 + lmA) * EE + kqA);
        else { wv.x = wv.y = wv.z = wv.w = 0.0f; }
        xv0 = *(const float4*)(g_X + (size_t)(n0 + tok) * EP + f4b * 4);
        xv1 = *(const float4*)(g_X + (size_t)(n0 + tok) * EP + f4b * 4 + 4);
    }
    As[0][kqA + 0][lmA] = pack2(wv.x, wv.x);
    As[0][kqA + 1][lmA] = pack2(wv.y, wv.y);
    As[0][kqA + 2][lmA] = pack2(wv.z, wv.z);
    As[0][kqA + 3][lmA] = pack2(wv.w, wv.w);
    Xs[0][f4b * 4 + 0][tok] = xv0.x; Xs[0][f4b * 4 + 1][tok] = xv0.y;
    Xs[0][f4b * 4 + 2][tok] = xv0.z; Xs[0][f4b * 4 + 3][tok] = xv0.w;
    Xs[0][f4b * 4 + 4][tok] = xv1.x; Xs[0][f4b * 4 + 5][tok] = xv1.y;
    Xs[0][f4b * 4 + 6][tok] = xv1.z; Xs[0][f4b * 4 + 7][tok] = xv1.w;
    __syncthreads();

    const int NTILE = EP / 16;
    for (int i = 0; i < NTILE; i++) {
        int cb = i & 1, nb = (i + 1) & 1;
        if (i + 1 < NTILE) {
            int e0 = (i + 1) * 16;
            if (e0 + kqA < EE) wv = *(const float4*)(Wih + (size_t)(m0 + lmA) * EE + e0 + kqA);
            else { wv.x = wv.y = wv.z = wv.w = 0.0f; }
            xv0 = *(const float4*)(g_X + (size_t)(n0 + tok) * EP + e0 + f4b * 4);
            xv1 = *(const float4*)(g_X + (size_t)(n0 + tok) * EP + e0 + f4b * 4 + 4);
        }
#pragma unroll
        for (int k = 0; k < 16; k++) {
            ulonglong2 wA = *(const ulonglong2*)&As[cb][k][ty * 2];
            ulonglong2 wB = *(const ulonglong2*)&As[cb][k][32 + ty * 2];
            ulonglong2 xA = *(const ulonglong2*)&Xs[cb][k][tx * 4];
            ulonglong2 xB = *(const ulonglong2*)&Xs[cb][k][64 + tx * 4];
            acc[0][0] = fma2(wA.x, xA.x, acc[0][0]); acc[0][1] = fma2(wA.x, xA.y, acc[0][1]);
            acc[0][2] = fma2(wA.x, xB.x, acc[0][2]); acc[0][3] = fma2(wA.x, xB.y, acc[0][3]);
            acc[1][0] = fma2(wA.y, xA.x, acc[1][0]); acc[1][1] = fma2(wA.y, xA.y, acc[1][1]);
            acc[1][2] = fma2(wA.y, xB.x, acc[1][2]); acc[1][3] = fma2(wA.y, xB.y, acc[1][3]);
            acc[2][0] = fma2(wB.x, xA.x, acc[2][0]); acc[2][1] = fma2(wB.x, xA.y, acc[2][1]);
            acc[2][2] = fma2(wB.x, xB.x, acc[2][2]); acc[2][3] = fma2(wB.x, xB.y, acc[2][3]);
            acc[3][0] = fma2(wB.y, xA.x, acc[3][0]); acc[3][1] = fma2(wB.y, xA.y, acc[3][1]);
            acc[3][2] = fma2(wB.y, xB.x, acc[3][2]); acc[3][3] = fma2(wB.y, xB.y, acc[3][3]);
        }
        if (i + 1 < NTILE) {
            As[nb][kqA + 0][lmA] = pack2(wv.x, wv.x);
            As[nb][kqA + 1][lmA] = pack2(wv.y, wv.y);
            As[nb][kqA + 2][lmA] = pack2(wv.z, wv.z);
            As[nb][kqA + 3][lmA] = pack2(wv.w, wv.w);
            Xs[nb][f4b * 4 + 0][tok] = xv0.x; Xs[nb][f4b * 4 + 1][tok] = xv0.y;
            Xs[nb][f4b * 4 + 2][tok] = xv0.z; Xs[nb][f4b * 4 + 3][tok] = xv0.w;
            Xs[nb][f4b * 4 + 4][tok] = xv1.x; Xs[nb][f4b * 4 + 5][tok] = xv1.y;
            Xs[nb][f4b * 4 + 6][tok] = xv1.z; Xs[nb][f4b * 4 + 7][tok] = xv1.w;
        }
        __syncthreads();
    }

    int rows[4] = {m0 + ty * 2, m0 + ty * 2 + 1, m0 + 32 + ty * 2, m0 + 33 + ty * 2};
#pragma unroll
    for (int i = 0; i < 4; i++) {
        int row = rows[i];
        float bias = bih[row] + bhh[row];
#pragma unroll
        for (int c = 0; c < 4; c++) {
            float2 f = *(float2*)&acc[i][c];
            int n = n0 + (c < 2 ? tx * 4 + c * 2 : 64 + tx * 4 + (c - 2) * 2);
            int tt = n >> 5, bb2 = n & 31;
            float2 o;
            o.x = f.x + bias; o.y = f.y + bias;
            *(float2*)&g_xg[(((size_t)d * SS + tt) * T4H + row) * BB + bb2] = o;
        }
    }
}

// ---------------- persistent BiLSTM recurrence (round-5 verbatim) ----------------
__global__ __launch_bounds__(128, 1) void lstm_kernel(
    const float* __restrict__ WhhF, const float* __restrict__ WhhB) {
    extern __shared__ ull sm8[];
    ull*   W_dup = sm8;
    float* h_s   = (float*)(sm8 + 4096);
    ull*   part  = sm8 + 8192;

    int tid = threadIdx.x, bid = blockIdx.x;
    int d = bid >> 6, m = bid & 63;
    const float* Whh = d ? WhhB : WhhF;

    for (int i = tid; i < 4096; i += 128) {
        int r = i & 15, k = i >> 4;
        int gg = r >> 2, uu = r & 3;
        float w = Whh[(size_t)(gg * HH + m * 4 + uu) * HH + k];
        W_dup[k * 16 + r] = pack2(w, w);
    }
    __syncthreads();

    int lane = tid & 31, w = tid >> 5;
    int ggl = lane & 3, bg = lane >> 2;
    const ulonglong2* Wd2 = (const ulonglong2*)W_dup;
    const ulonglong2* H2  = (const ulonglong2*)h_s;
    int u = tid >> 5, b = tid & 31;
    float c_reg = 0.0f;
    unsigned* barD = g_bar + d * SS * 4;
    int mygrp = m >> 4;

    for (int it = 0; it < SS; it++) {
        int t = d ? (SS - 1 - it) : it;

        float xgv[4];
        const float* xgb = g_xg + ((size_t)(d * SS + t) * T4H) * BB;
#pragma unroll
        for (int gg = 0; gg < 4; gg++)
            xgv[gg] = xgb[(size_t)(gg * HH + m * 4 + u) * BB + b];

        if (it > 0) {
            unsigned* cp = barD + (it - 1) * 4 + w;
            unsigned v;
            do {
                asm volatile("ld.acquire.gpu.global.u32 %0, [%1];" : "=r"(v) : "l"(cp) : "memory");
            } while (v < 16u);

            int tp = d ? t + 1 : t - 1;
            const float4* src4 = (const float4*)(g_h + (size_t)(d * SS + tp) * HH * BB);
            float4* dst4 = (float4*)h_s;
#pragma unroll
            for (int j = 0; j < 16; j++) {
                int idx = w * 512 + lane + j * 32;
                dst4[idx] = src4[idx];
            }
            __syncwarp();

            ull a[4][2];
#pragma unroll
            for (int i = 0; i < 4; i++) { a[i][0] = 0ULL; a[i][1] = 0ULL; }
            int k0 = w * 64;
#pragma unroll 8
            for (int k = k0; k < k0 + 64; k++) {
                ulonglong2 w01 = Wd2[k * 8 + ggl * 2];
                ulonglong2 w23 = Wd2[k * 8 + ggl * 2 + 1];
                ulonglong2 hh  = H2[k * 8 + bg];
                a[0][0] = fma2(w01.x, hh.x, a[0][0]); a[0][1] = fma2(w01.x, hh.y, a[0][1]);
                a[1][0] = fma2(w01.y, hh.x, a[1][0]); a[1][1] = fma2(w01.y, hh.y, a[1][1]);
                a[2][0] = fma2(w23.x, hh.x, a[2][0]); a[2][1] = fma2(w23.x, hh.y, a[2][1]);
                a[3][0] = fma2(w23.y, hh.x, a[3][0]); a[3][1] = fma2(w23.y, hh.y, a[3][1]);
            }
#pragma unroll
            for (int i = 0; i < 4; i++) {
                ull* pr = part + (size_t)(w * 16 + ggl * 4 + i) * 17 + bg * 2;
                pr[0] = a[i][0]; pr[1] = a[i][1];
            }
        }
        __syncthreads();

        {
            const float* pf = (const float*)part;
            float g[4];
#pragma unroll
            for (int gg = 0; gg < 4; gg++) {
                float s = xgv[gg];
                if (it > 0) {
                    int r = gg * 4 + u;
#pragma unroll
                    for (int wi = 0; wi < 4; wi++)
                        s += pf[(((size_t)wi * 16 + r) * 17 + (b >> 1)) * 2 + (b & 1)];
                }
                g[gg] = s;
            }
            float iv = fsigmoid(g[0]);
            float fv = fsigmoid(g[1]);
            float gv = ftanh_fast(g[2]);
            float ov = fsigmoid(g[3]);
            c_reg = fv * c_reg + iv * gv;
            g_h[((size_t)(d * SS + t) * HH + m * 4 + u) * BB + b] = ov * ftanh_fast(c_reg);
        }
        __syncthreads();

        if (tid == 0) {
            unsigned* ap = barD + it * 4 + mygrp;
            asm volatile("red.release.gpu.global.add.u32 [%0], %1;" :: "l"(ap), "r"(1u) : "memory");
        }
    }
}

// ---------------- logits: Wtag staged in smem ----------------
__global__ __launch_bounds__(256) void logits_kernel(const float* __restrict__ Wtag,
                                                     const float* __restrict__ btag) {
    extern __shared__ float hb[];
    float* wt = hb + 512 * 32;
    int t = blockIdx.x;
    int tid = threadIdx.x;
    for (int dd = 0; dd < 2; dd++) {
        const float4* src = (const float4*)(g_h + (size_t)(dd * SS + t) * HH * BB);
        float4* dst = (float4*)(hb + (size_t)dd * HH * BB);
        for (int i = tid; i < 2048; i += 256) dst[i] = src[i];
    }
    {
        const float4* ws = (const float4*)Wtag;
        float4* wd = (float4*)wt;
        for (int i = tid; i < 2432; i += 256) wd[i] = ws[i];
    }
    __syncthreads();
    for (int o = tid; o < BB * NT; o += 256) {
        int tag = o >> 5;
        int b = o & 31;
        float acc = btag[tag];
        const float* wr = wt + tag * 512;
#pragma unroll 8
        for (int k = 0; k < 2 * HH; k++) acc += hb[k * BB + b] * wr[k];
        g_logits[((size_t)b * SS + t) * NT + tag] = acc;
    }
}

// ---------------- merged CRF forward + Viterbi, smem-staged, exp-hoisted ----------------
// CRF per step: logsumexp_i(a_i + T_ij) = mx + log(sum_i exp(a_i-mx) * E_ij),
// E_ij = exp(T_ij) precomputed into per-thread registers -> ONE expf per lane per step.
__global__ void crf_vit_kernel(const int* __restrict__ mask, const int* __restrict__ labels,
                               const float* __restrict__ trans, float* __restrict__ out) {
    extern __shared__ float smc[];
    float* tr  = smc;                      // [361]
    float* lg  = smc + 364;                // logits for this b: [t*NT+j]
    int*   msk = (int*)(smc + 364 + 4864);
    int*   lbl = msk + 256;
    int*   ptr_s = msk + 512;
    __shared__ float st[NT];
    __shared__ float p[NT];

    int b = blockIdx.x, j = threadIdx.x;
    for (int i = j; i < NT * NT; i += 32) tr[i] = trans[i];
    {
        const float4* src = (const float4*)(g_logits + (size_t)b * SS * NT);
        float4* dst = (float4*)lg;
        for (int i = j; i < SS * NT / 4; i += 32) dst[i] = src[i];
    }
    for (int i = j; i < SS; i += 32) {
        msk[i] = mask[b * SS + i];
        lbl[i] = labels[b * SS + i];
    }
    __syncthreads();

    if (blockIdx.y == 0) {
        // ---- CRF NLL (exp-hoisted) ----
        float Ecol[NT];
        if (j < NT) {
#pragma unroll
            for (int i = 0; i < NT; i++) Ecol[i] = __expf(tr[i * NT + j]);
            st[j] = lg[j] + tr[TSTART * NT + j];
        }
        __syncthreads();
        for (int t = 1; t < SS; t++) {
            int mt = msk[t];
            float mx = -1e30f, nv = 0.0f;
            if (j < NT) {
#pragma unroll
                for (int i = 0; i < NT; i++) mx = fmaxf(mx, st[i]);
                p[j] = __expf(st[j] - mx);
            }
            __syncthreads();
            if (j < NT) {
                float s = 0.0f;
#pragma unroll
                for (int i = 0; i < NT; i++) s += p[i] * Ecol[i];
                nv = mx + __logf(s) + lg[t * NT + j];
            }
            __syncthreads();
            if (j < NT && mt > 0) st[j] = nv;
            __syncthreads();
        }
        if (j == 0) {
            float mx = -1e30f;
            for (int i = 0; i < NT; i++) mx = fmaxf(mx, st[i] + tr[i * NT + TSTOP]);
            float sum = 0.0f;
            for (int i = 0; i < NT; i++) sum += __expf(st[i] + tr[i * NT + TSTOP] - mx);
            float logZ = mx + __logf(sum);
            float gold = 0.0f;
            int prev = TSTART, len = 0;
            for (int t = 0; t < SS; t++) {
                int lab = lbl[t];
                if (msk[t] > 0) {
                    gold += tr[prev * NT + lab] + lg[t * NT + lab];
                    len++;
                }
                prev = lab;
            }
            int last = lbl[len - 1];
            gold += tr[last * NT + TSTOP];
            atomicAdd(out, (logZ - gold) * (1.0f / (float)BB));
        }
    } else {
        // ---- Viterbi (T column hoisted to registers) ----
        float Tcol[NT];
        if (j < NT) {
#pragma unroll
            for (int i = 0; i < NT; i++) Tcol[i] = tr[i * NT + j];
            st[j] = lg[j] + tr[TSTART * NT + j];
        }
        __syncthreads();
        for (int t = 1; t < SS; t++) {
            int mt = msk[t];
            float nv = 0.0f;
            int arg = j;
            if (j < NT) {
                float best = -1e30f;
                int bi = 0;
#pragma unroll
                for (int i = 0; i < NT; i++) {
                    float v = st[i] + Tcol[i];
                    if (v > best) { best = v; bi = i; }  // strict '>' => first max (jnp.argmax)
                }
                nv = best + lg[t * NT + j];
                if (mt > 0) arg = bi;
            }
            __syncthreads();
            if (j < NT) {
                if (mt > 0) st[j] = nv;
                ptr_s[t * NT + j] = arg;
            }
            __syncthreads();
        }
        if (j == 0) {
            float best = -1e30f;
            int bl = 0;
            for (int i = 0; i < NT; i++) {
                float v = st[i] + tr[i * NT + TSTOP];
                if (v > best) { best = v; bl = i; }
            }
            int tag = bl;
            for (int t = SS - 1; t >= 1; t--) {
                out[1 + b * SS + t] = (float)(msk[t] > 0 ? tag : 0);
                tag = ptr_s[t * NT + tag];
            }
            out[1 + b * SS + 0] = (float)(msk[0] > 0 ? tag : 0);
        }
    }
}

extern "C" void kernel_launch(void* const* d_in, const int* in_sizes, int n_in,
                              void* d_out, int out_size) {
    int o = (in_sizes[4] == 1) ? 0 : -1;
    const int*   word   = (const int*)d_in[0];
    const int*   mask   = (const int*)d_in[1];
    const int*   labels = (const int*)d_in[2];
    const float* emb    = (const float*)d_in[5 + o];
    const float* WihF   = (const float*)d_in[6 + o];
    const float* WhhF   = (const float*)d_in[7 + o];
    const float* bihF   = (const float*)d_in[8 + o];
    const float* bhhF   = (const float*)d_in[9 + o];
    const float* WihB   = (const float*)d_in[10 + o];
    const float* WhhB   = (const float*)d_in[11 + o];
    const float* bihB   = (const float*)d_in[12 + o];
    const float* bhhB   = (const float*)d_in[13 + o];
    const float* Wtag   = (const float*)d_in[14 + o];
    const float* btag   = (const float*)d_in[15 + o];
    const float* trans  = (const float*)d_in[16 + o];
    float* out = (float*)d_out;

    const int lstm_smem = (4096 + 4096 + 1088) * 8;
    const int logits_smem = (512 * 32 + 19 * 512) * 4;
    const int crf_smem = (364 + 4864 + 256 + 256 + 4864) * 4;
    cudaFuncSetAttribute(lstm_kernel, cudaFuncAttributeMaxDynamicSharedMemorySize, lstm_smem);
    cudaFuncSetAttribute(logits_kernel, cudaFuncAttributeMaxDynamicSharedMemorySize, logits_smem);

    embed_kernel<<<(BB * SS * (EP / 4) + 255) / 256, 256>>>(word, mask, emb, out);
    {
        dim3 grid(BB * SS / 128, T4H / 64, 2);
        gemm_xg_kernel<<<grid, 256>>>(WihF, WihB, bihF, bhhF, bihB, bhhB);
    }
    lstm_kernel<<<128, 128, lstm_smem>>>(WhhF, WhhB);
    logits_kernel<<<SS, 256, logits_smem>>>(Wtag, btag);
    crf_vit_kernel<<<dim3(BB, 2), 32, crf_smem>>>(mask, labels, trans, out);
}

// round 16
// speedup vs baseline: 1.0579x; 1.0247x over previous
#include <cuda_runtime.h>
#include <math.h>

#define BB 32
#define SS 256
#define EE 300
#define EP 304
#define HH 256
#define T4H 1024
#define NT 19
#define TSTART 17
#define TSTOP 18

typedef unsigned long long ull;

__device__ __forceinline__ ull fma2(ull a, ull b, ull c) {
    ull d;
    asm("fma.rn.f32x2 %0, %1, %2, %3;" : "=l"(d) : "l"(a), "l"(b), "l"(c));
    return d;
}
__device__ __forceinline__ ull pack2(float lo, float hi) {
    ull r;
    asm("mov.b64 %0, {%1, %2};" : "=l"(r) : "f"(lo), "f"(hi));
    return r;
}
__device__ __forceinline__ float fsigmoid(float x) {
    return 1.0f / (1.0f + __expf(-x));
}
__device__ __forceinline__ float ftanh_fast(float x) {
    return 1.0f - 2.0f / (__expf(2.0f * x) + 1.0f);
}

// ---------------- device scratch (no cudaMalloc allowed) ----------------
__device__ float    g_X[(size_t)BB * SS * EP];            // [n][e], n = t*32 + b
__device__ float    g_xg[(size_t)2 * SS * T4H * BB];      // [d][t][row][b]
__device__ float    g_h[(size_t)2 * SS * HH * BB];        // [d][t][k][b]
__device__ float    g_logits[(size_t)BB * SS * NT];       // [b][t*NT+tag]
__device__ unsigned g_bar[2 * SS * 4];                    // [dir][step][group] arrival counters

// ---------------- embedding gather + mask -> padded X; inits out[0] + counters ----------------
__global__ void embed_kernel(const int* __restrict__ word, const int* __restrict__ mask,
                             const float* __restrict__ emb, float* __restrict__ out) {
    int idx = blockIdx.x * blockDim.x + threadIdx.x;
    if (idx == 0) out[0] = 0.0f;
    if (idx < 2 * SS * 4) g_bar[idx] = 0u;
    int total = BB * SS * (EP / 4);
    if (idx >= total) return;
    int n = idx / (EP / 4), q = idx - n * (EP / 4);
    int t = n >> 5, b = n & 31;
    int w = word[b * SS + t];
    float m = (float)mask[b * SS + t];
    int e = q * 4;
    float4 v;
    if (e < EE) {
        float4 ev = *(const float4*)(emb + (size_t)w * EE + e);
        v.x = ev.x * m; v.y = ev.y * m; v.z = ev.z * m; v.w = ev.w * m;
    } else {
        v.x = v.y = v.z = v.w = 0.0f;
    }
    ((float4*)g_X)[(size_t)n * (EP / 4) + q] = v;
}

// ---------------- input-transform GEMM: double-buffered, conflict-free f32x2 (R13) ----------------
__global__ __launch_bounds__(256) void gemm_xg_kernel(
    const float* __restrict__ WihF, const float* __restrict__ WihB,
    const float* __restrict__ bihF, const float* __restrict__ bhhF,
    const float* __restrict__ bihB, const float* __restrict__ bhhB) {
    __shared__ ull   As[2][16][64];
    __shared__ float Xs[2][16][132];
    int d = blockIdx.z;
    const float* Wih = d ? WihB : WihF;
    const float* bih = d ? bihB : bihF;
    const float* bhh = d ? bhhB : bhhF;
    int m0 = blockIdx.y * 64, n0 = blockIdx.x * 128;
    int tid = threadIdx.x;
    int lmA = tid >> 2, kqA = (tid & 3) * 4;
    int tok = tid >> 1, f4b = (tid & 1) * 2;
    int tx = tid & 15, ty = tid >> 4;

    ull acc[4][4];
#pragma unroll
    for (int i = 0; i < 4; i++)
#pragma unroll
        for (int j = 0; j < 4; j++) acc[i][j] = 0ULL;

    float4 wv, xv0, xv1;
    {
        if (kqA < EE) wv = *(const float4*)(Wih + (size_t)(m0 + lmA) * EE + kqA);
        else { wv.x = wv.y = wv.z = wv.w = 0.0f; }
        xv0 = *(const float4*)(g_X + (size_t)(n0 + tok) * EP + f4b * 4);
        xv1 = *(const float4*)(g_X + (size_t)(n0 + tok) * EP + f4b * 4 + 4);
    }
    As[0][kqA + 0][lmA] = pack2(wv.x, wv.x);
    As[0][kqA + 1][lmA] = pack2(wv.y, wv.y);
    As[0][kqA + 2][lmA] = pack2(wv.z, wv.z);
    As[0][kqA + 3][lmA] = pack2(wv.w, wv.w);
    Xs[0][f4b * 4 + 0][tok] = xv0.x; Xs[0][f4b * 4 + 1][tok] = xv0.y;
    Xs[0][f4b * 4 + 2][tok] = xv0.z; Xs[0][f4b * 4 + 3][tok] = xv0.w;
    Xs[0][f4b * 4 + 4][tok] = xv1.x; Xs[0][f4b * 4 + 5][tok] = xv1.y;
    Xs[0][f4b * 4 + 6][tok] = xv1.z; Xs[0][f4b * 4 + 7][tok] = xv1.w;
    __syncthreads();

    const int NTILE = EP / 16;
    for (int i = 0; i < NTILE; i++) {
        int cb = i & 1, nb = (i + 1) & 1;
        if (i + 1 < NTILE) {
            int e0 = (i + 1) * 16;
            if (e0 + kqA < EE) wv = *(const float4*)(Wih + (size_t)(m0 + lmA) * EE + e0 + kqA);
            else { wv.x = wv.y = wv.z = wv.w = 0.0f; }
            xv0 = *(const float4*)(g_X + (size_t)(n0 + tok) * EP + e0 + f4b * 4);
            xv1 = *(const float4*)(g_X + (size_t)(n0 + tok) * EP + e0 + f4b * 4 + 4);
        }
#pragma unroll
        for (int k = 0; k < 16; k++) {
            ulonglong2 wA = *(const ulonglong2*)&As[cb][k][ty * 2];
            ulonglong2 wB = *(const ulonglong2*)&As[cb][k][32 + ty * 2];
            ulonglong2 xA = *(const ulonglong2*)&Xs[cb][k][tx * 4];
            ulonglong2 xB = *(const ulonglong2*)&Xs[cb][k][64 + tx * 4];
            acc[0][0] = fma2(wA.x, xA.x, acc[0][0]); acc[0][1] = fma2(wA.x, xA.y, acc[0][1]);
            acc[0][2] = fma2(wA.x, xB.x, acc[0][2]); acc[0][3] = fma2(wA.x, xB.y, acc[0][3]);
            acc[1][0] = fma2(wA.y, xA.x, acc[1][0]); acc[1][1] = fma2(wA.y, xA.y, acc[1][1]);
            acc[1][2] = fma2(wA.y, xB.x, acc[1][2]); acc[1][3] = fma2(wA.y, xB.y, acc[1][3]);
            acc[2][0] = fma2(wB.x, xA.x, acc[2][0]); acc[2][1] = fma2(wB.x, xA.y, acc[2][1]);
            acc[2][2] = fma2(wB.x, xB.x, acc[2][2]); acc[2][3] = fma2(wB.x, xB.y, acc[2][3]);
            acc[3][0] = fma2(wB.y, xA.x, acc[3][0]); acc[3][1] = fma2(wB.y, xA.y, acc[3][1]);
            acc[3][2] = fma2(wB.y, xB.x, acc[3][2]); acc[3][3] = fma2(wB.y, xB.y, acc[3][3]);
        }
        if (i + 1 < NTILE) {
            As[nb][kqA + 0][lmA] = pack2(wv.x, wv.x);
            As[nb][kqA + 1][lmA] = pack2(wv.y, wv.y);
            As[nb][kqA + 2][lmA] = pack2(wv.z, wv.z);
            As[nb][kqA + 3][lmA] = pack2(wv.w, wv.w);
            Xs[nb][f4b * 4 + 0][tok] = xv0.x; Xs[nb][f4b * 4 + 1][tok] = xv0.y;
            Xs[nb][f4b * 4 + 2][tok] = xv0.z; Xs[nb][f4b * 4 + 3][tok] = xv0.w;
            Xs[nb][f4b * 4 + 4][tok] = xv1.x; Xs[nb][f4b * 4 + 5][tok] = xv1.y;
            Xs[nb][f4b * 4 + 6][tok] = xv1.z; Xs[nb][f4b * 4 + 7][tok] = xv1.w;
        }
        __syncthreads();
    }

    int rows[4] = {m0 + ty * 2, m0 + ty * 2 + 1, m0 + 32 + ty * 2, m0 + 33 + ty * 2};
#pragma unroll
    for (int i = 0; i < 4; i++) {
        int row = rows[i];
        float bias = bih[row] + bhh[row];
#pragma unroll
        for (int c = 0; c < 4; c++) {
            float2 f = *(float2*)&acc[i][c];
            int n = n0 + (c < 2 ? tx * 4 + c * 2 : 64 + tx * 4 + (c - 2) * 2);
            int tt = n >> 5, bb2 = n & 31;
            float2 o;
            o.x = f.x + bias; o.y = f.y + bias;
            *(float2*)&g_xg[(((size_t)d * SS + tt) * T4H + row) * BB + bb2] = o;
        }
    }
}

// ---------------- persistent BiLSTM: 256 threads, 8-warp GEMV, R5 flag protocol ----------------
// 128 blocks: bid>>6 = dir, m = bid&63 owns units [4m,4m+4) -> 16 gate rows.
// Warp w (0..7) handles k in [32w,32w+32); producers of that k-range are blocks
// [8w,8w+8) which lie in flag-group (w>>1) -> warp polls group counter (target 16).
__global__ __launch_bounds__(256, 1) void lstm_kernel(
    const float* __restrict__ WhhF, const float* __restrict__ WhhB) {
    extern __shared__ ull sm8[];
    ull*   W_dup = sm8;                     // [256 k][16 r] {w,w} pairs (4096 ull)
    float* h_s   = (float*)(sm8 + 4096);    // [256 k][32 b]            (4096 ull)
    ull*   part  = sm8 + 8192;              // [8 w][16 r][17 pairs]    (2176 ull)

    int tid = threadIdx.x, bid = blockIdx.x;
    int d = bid >> 6, m = bid & 63;
    const float* Whh = d ? WhhB : WhhF;

    for (int i = tid; i < 4096; i += 256) {
        int r = i & 15, k = i >> 4;
        int gg = r >> 2, uu = r & 3;
        float w = Whh[(size_t)(gg * HH + m * 4 + uu) * HH + k];
        W_dup[k * 16 + r] = pack2(w, w);
    }
    __syncthreads();

    int lane = tid & 31, w = tid >> 5;       // w in 0..7
    int ggl = lane & 3, bg = lane >> 2;
    const ulonglong2* Wd2 = (const ulonglong2*)W_dup;
    const ulonglong2* H2  = (const ulonglong2*)h_s;
    int u = tid >> 5, b = tid & 31;          // cell mapping (tid < 128): u 0..3
    float c_reg = 0.0f;
    unsigned* barD = g_bar + d * SS * 4;
    int mygrp = m >> 4;

    for (int it = 0; it < SS; it++) {
        int t = d ? (SS - 1 - it) : it;

        float xgv[4];
        if (tid < 128) {
            const float* xgb = g_xg + ((size_t)(d * SS + t) * T4H) * BB;
#pragma unroll
            for (int gg = 0; gg < 4; gg++)
                xgv[gg] = xgb[(size_t)(gg * HH + m * 4 + u) * BB + b];
        }

        if (it > 0) {
            // warp w waits for flag-group (w>>1): covers producers of k in [32w,32w+32)
            unsigned* cp = barD + (it - 1) * 4 + (w >> 1);
            unsigned v;
            do {
                asm volatile("ld.acquire.gpu.global.u32 %0, [%1];" : "=r"(v) : "l"(cp) : "memory");
            } while (v < 16u);

            // stage this warp's 32-k slice (4KB, 8 float4/lane)
            int tp = d ? t + 1 : t - 1;
            const float4* src4 = (const float4*)(g_h + (size_t)(d * SS + tp) * HH * BB);
            float4* dst4 = (float4*)h_s;
#pragma unroll
            for (int j = 0; j < 8; j++) {
                int idx = w * 256 + j * 32 + lane;
                dst4[idx] = src4[idx];
            }
            __syncwarp();

            ull a[4][2];
#pragma unroll
            for (int i = 0; i < 4; i++) { a[i][0] = 0ULL; a[i][1] = 0ULL; }
            int k0 = w * 32;
#pragma unroll 8
            for (int k = k0; k < k0 + 32; k++) {
                ulonglong2 w01 = Wd2[k * 8 + ggl * 2];
                ulonglong2 w23 = Wd2[k * 8 + ggl * 2 + 1];
                ulonglong2 hh  = H2[k * 8 + bg];
                a[0][0] = fma2(w01.x, hh.x, a[0][0]); a[0][1] = fma2(w01.x, hh.y, a[0][1]);
                a[1][0] = fma2(w01.y, hh.x, a[1][0]); a[1][1] = fma2(w01.y, hh.y, a[1][1]);
                a[2][0] = fma2(w23.x, hh.x, a[2][0]); a[2][1] = fma2(w23.x, hh.y, a[2][1]);
                a[3][0] = fma2(w23.y, hh.x, a[3][0]); a[3][1] = fma2(w23.y, hh.y, a[3][1]);
            }
#pragma unroll
            for (int i = 0; i < 4; i++) {
                ull* pr = part + (size_t)(w * 16 + ggl * 4 + i) * 17 + bg * 2;
                pr[0] = a[i][0]; pr[1] = a[i][1];
            }
        }
        __syncthreads();

        if (tid < 128) {
            const float* pf = (const float*)part;
            float g[4];
#pragma unroll
            for (int gg = 0; gg < 4; gg++) {
                float s = xgv[gg];
                if (it > 0) {
                    int r = gg * 4 + u;
#pragma unroll
                    for (int wi = 0; wi < 8; wi++)
                        s += pf[(((size_t)wi * 16 + r) * 17 + (b >> 1)) * 2 + (b & 1)];
                }
                g[gg] = s;
            }
            float iv = fsigmoid(g[0]);
            float fv = fsigmoid(g[1]);
            float gv = ftanh_fast(g[2]);
            float ov = fsigmoid(g[3]);
            c_reg = fv * c_reg + iv * gv;
            g_h[((size_t)(d * SS + t) * HH + m * 4 + u) * BB + b] = ov * ftanh_fast(c_reg);
        }
        __syncthreads();

        if (tid == 0) {
            unsigned* ap = barD + it * 4 + mygrp;
            asm volatile("red.release.gpu.global.add.u32 [%0], %1;" :: "l"(ap), "r"(1u) : "memory");
        }
    }
}

// ---------------- logits: Wtag staged in smem ----------------
__global__ __launch_bounds__(256) void logits_kernel(const float* __restrict__ Wtag,
                                                     const float* __restrict__ btag) {
    extern __shared__ float hb[];
    float* wt = hb + 512 * 32;
    int t = blockIdx.x;
    int tid = threadIdx.x;
    for (int dd = 0; dd < 2; dd++) {
        const float4* src = (const float4*)(g_h + (size_t)(dd * SS + t) * HH * BB);
        float4* dst = (float4*)(hb + (size_t)dd * HH * BB);
        for (int i = tid; i < 2048; i += 256) dst[i] = src[i];
    }
    {
        const float4* ws = (const float4*)Wtag;
        float4* wd = (float4*)wt;
        for (int i = tid; i < 2432; i += 256) wd[i] = ws[i];
    }
    __syncthreads();
    for (int o = tid; o < BB * NT; o += 256) {
        int tag = o >> 5;
        int b = o & 31;
        float acc = btag[tag];
        const float* wr = wt + tag * 512;
#pragma unroll 8
        for (int k = 0; k < 2 * HH; k++) acc += hb[k * BB + b] * wr[k];
        g_logits[((size_t)b * SS + t) * NT + tag] = acc;
    }
}

// ---------------- merged CRF forward + Viterbi, smem-staged, exp-hoisted ----------------
__global__ void crf_vit_kernel(const int* __restrict__ mask, const int* __restrict__ labels,
                               const float* __restrict__ trans, float* __restrict__ out) {
    extern __shared__ float smc[];
    float* tr  = smc;
    float* lg  = smc + 364;
    int*   msk = (int*)(smc + 364 + 4864);
    int*   lbl = msk + 256;
    int*   ptr_s = msk + 512;
    __shared__ float st[NT];
    __shared__ float p[NT];

    int b = blockIdx.x, j = threadIdx.x;
    for (int i = j; i < NT * NT; i += 32) tr[i] = trans[i];
    {
        const float4* src = (const float4*)(g_logits + (size_t)b * SS * NT);
        float4* dst = (float4*)lg;
        for (int i = j; i < SS * NT / 4; i += 32) dst[i] = src[i];
    }
    for (int i = j; i < SS; i += 32) {
        msk[i] = mask[b * SS + i];
        lbl[i] = labels[b * SS + i];
    }
    __syncthreads();

    if (blockIdx.y == 0) {
        float Ecol[NT];
        if (j < NT) {
#pragma unroll
            for (int i = 0; i < NT; i++) Ecol[i] = __expf(tr[i * NT + j]);
            st[j] = lg[j] + tr[TSTART * NT + j];
        }
        __syncthreads();
        for (int t = 1; t < SS; t++) {
            int mt = msk[t];
            float mx = -1e30f, nv = 0.0f;
            if (j < NT) {
#pragma unroll
                for (int i = 0; i < NT; i++) mx = fmaxf(mx, st[i]);
                p[j] = __expf(st[j] - mx);
            }
            __syncthreads();
            if (j < NT) {
                float s = 0.0f;
#pragma unroll
                for (int i = 0; i < NT; i++) s += p[i] * Ecol[i];
                nv = mx + __logf(s) + lg[t * NT + j];
            }
            __syncthreads();
            if (j < NT && mt > 0) st[j] = nv;
            __syncthreads();
        }
        if (j == 0) {
            float mx = -1e30f;
            for (int i = 0; i < NT; i++) mx = fmaxf(mx, st[i] + tr[i * NT + TSTOP]);
            float sum = 0.0f;
            for (int i = 0; i < NT; i++) sum += __expf(st[i] + tr[i * NT + TSTOP] - mx);
            float logZ = mx + __logf(sum);
            float gold = 0.0f;
            int prev = TSTART, len = 0;
            for (int t = 0; t < SS; t++) {
                int lab = lbl[t];
                if (msk[t] > 0) {
                    gold += tr[prev * NT + lab] + lg[t * NT + lab];
                    len++;
                }
                prev = lab;
            }
            int last = lbl[len - 1];
            gold += tr[last * NT + TSTOP];
            atomicAdd(out, (logZ - gold) * (1.0f / (float)BB));
        }
    } else {
        float Tcol[NT];
        if (j < NT) {
#pragma unroll
            for (int i = 0; i < NT; i++) Tcol[i] = tr[i * NT + j];
            st[j] = lg[j] + tr[TSTART * NT + j];
        }
        __syncthreads();
        for (int t = 1; t < SS; t++) {
            int mt = msk[t];
            float nv = 0.0f;
            int arg = j;
            if (j < NT) {
                float best = -1e30f;
                int bi = 0;
#pragma unroll
                for (int i = 0; i < NT; i++) {
                    float v = st[i] + Tcol[i];
                    if (v > best) { best = v; bi = i; }  // strict '>' => first max (jnp.argmax)
                }
                nv = best + lg[t * NT + j];
                if (mt > 0) arg = bi;
            }
            __syncthreads();
            if (j < NT) {
                if (mt > 0) st[j] = nv;
                ptr_s[t * NT + j] = arg;
            }
            __syncthreads();
        }
        if (j == 0) {
            float best = -1e30f;
            int bl = 0;
            for (int i = 0; i < NT; i++) {
                float v = st[i] + tr[i * NT + TSTOP];
                if (v > best) { best = v; bl = i; }
            }
            int tag = bl;
            for (int t = SS - 1; t >= 1; t--) {
                out[1 + b * SS + t] = (float)(msk[t] > 0 ? tag : 0);
                tag = ptr_s[t * NT + tag];
            }
            out[1 + b * SS + 0] = (float)(msk[0] > 0 ? tag : 0);
        }
    }
}

extern "C" void kernel_launch(void* const* d_in, const int* in_sizes, int n_in,
                              void* d_out, int out_size) {
    int o = (in_sizes[4] == 1) ? 0 : -1;
    const int*   word   = (const int*)d_in[0];
    const int*   mask   = (const int*)d_in[1];
    const int*   labels = (const int*)d_in[2];
    const float* emb    = (const float*)d_in[5 + o];
    const float* WihF   = (const float*)d_in[6 + o];
    const float* WhhF   = (const float*)d_in[7 + o];
    const float* bihF   = (const float*)d_in[8 + o];
    const float* bhhF   = (const float*)d_in[9 + o];
    const float* WihB   = (const float*)d_in[10 + o];
    const float* WhhB   = (const float*)d_in[11 + o];
    const float* bihB   = (const float*)d_in[12 + o];
    const float* bhhB   = (const float*)d_in[13 + o];
    const float* Wtag   = (const float*)d_in[14 + o];
    const float* btag   = (const float*)d_in[15 + o];
    const float* trans  = (const float*)d_in[16 + o];
    float* out = (float*)d_out;

    const int lstm_smem = (4096 + 4096 + 2176) * 8;           // 82944 B
    const int logits_smem = (512 * 32 + 19 * 512) * 4;        // 104448 B
    const int crf_smem = (364 + 4864 + 256 + 256 + 4864) * 4; // 42416 B
    cudaFuncSetAttribute(lstm_kernel, cudaFuncAttributeMaxDynamicSharedMemorySize, lstm_smem);
    cudaFuncSetAttribute(logits_kernel, cudaFuncAttributeMaxDynamicSharedMemorySize, logits_smem);

    embed_kernel<<<(BB * SS * (EP / 4) + 255) / 256, 256>>>(word, mask, emb, out);
    {
        dim3 grid(BB * SS / 128, T4H / 64, 2);
        gemm_xg_kernel<<<grid, 256>>>(WihF, WihB, bihF, bhhF, bihB, bhhB);
    }
    lstm_kernel<<<128, 256, lstm_smem>>>(WhhF, WhhB);
    logits_kernel<<<SS, 256, logits_smem>>>(Wtag, btag);
    crf_vit_kernel<<<dim3(BB, 2), 32, crf_smem>>>(mask, labels, trans, out);
}

// round 17
// speedup vs baseline: 1.0613x; 1.0032x over previous
#include <cuda_runtime.h>
#include <math.h>

#define BB 32
#define SS 256
#define EE 300
#define EP 304
#define HH 256
#define T4H 1024
#define NT 19
#define TSTART 17
#define TSTOP 18

typedef unsigned long long ull;

__device__ __forceinline__ ull fma2(ull a, ull b, ull c) {
    ull d;
    asm("fma.rn.f32x2 %0, %1, %2, %3;" : "=l"(d) : "l"(a), "l"(b), "l"(c));
    return d;
}
__device__ __forceinline__ ull pack2(float lo, float hi) {
    ull r;
    asm("mov.b64 %0, {%1, %2};" : "=l"(r) : "f"(lo), "f"(hi));
    return r;
}
__device__ __forceinline__ float fsigmoid(float x) {
    return 1.0f / (1.0f + __expf(-x));
}
__device__ __forceinline__ float ftanh_fast(float x) {
    return 1.0f - 2.0f / (__expf(2.0f * x) + 1.0f);
}

// ---------------- device scratch (no cudaMalloc allowed) ----------------
__device__ float    g_X[(size_t)BB * SS * EP];            // [n][e], n = t*32 + b
__device__ float    g_xg[(size_t)2 * SS * T4H * BB];      // [d][t][row][b]
__device__ float    g_h[(size_t)2 * SS * HH * BB];        // [d][t][k][b]
__device__ float    g_logits[(size_t)BB * SS * NT];       // [b][t*NT+tag]
__device__ unsigned g_bar[2 * SS * 4];                    // [dir][step][group] arrival counters

// ---------------- embedding gather + mask -> padded X; inits out[0] + counters ----------------
__global__ void embed_kernel(const int* __restrict__ word, const int* __restrict__ mask,
                             const float* __restrict__ emb, float* __restrict__ out) {
    int idx = blockIdx.x * blockDim.x + threadIdx.x;
    if (idx == 0) out[0] = 0.0f;
    if (idx < 2 * SS * 4) g_bar[idx] = 0u;
    int total = BB * SS * (EP / 4);
    if (idx >= total) return;
    int n = idx / (EP / 4), q = idx - n * (EP / 4);
    int t = n >> 5, b = n & 31;
    int w = word[b * SS + t];
    float m = (float)mask[b * SS + t];
    int e = q * 4;
    float4 v;
    if (e < EE) {
        float4 ev = *(const float4*)(emb + (size_t)w * EE + e);
        v.x = ev.x * m; v.y = ev.y * m; v.z = ev.z * m; v.w = ev.w * m;
    } else {
        v.x = v.y = v.z = v.w = 0.0f;
    }
    ((float4*)g_X)[(size_t)n * (EP / 4) + q] = v;
}

// ---------------- input-transform GEMM: double-buffered, conflict-free f32x2 (R13) ----------------
__global__ __launch_bounds__(256) void gemm_xg_kernel(
    const float* __restrict__ WihF, const float* __restrict__ WihB,
    const float* __restrict__ bihF, const float* __restrict__ bhhF,
    const float* __restrict__ bihB, const float* __restrict__ bhhB) {
    __shared__ ull   As[2][16][64];
    __shared__ float Xs[2][16][132];
    int d = blockIdx.z;
    const float* Wih = d ? WihB : WihF;
    const float* bih = d ? bihB : bihF;
    const float* bhh = d ? bhhB : bhhF;
    int m0 = blockIdx.y * 64, n0 = blockIdx.x * 128;
    int tid = threadIdx.x;
    int lmA = tid >> 2, kqA = (tid & 3) * 4;
    int tok = tid >> 1, f4b = (tid & 1) * 2;
    int tx = tid & 15, ty = tid >> 4;

    ull acc[4][4];
#pragma unroll
    for (int i = 0; i < 4; i++)
#pragma unroll
        for (int j = 0; j < 4; j++) acc[i][j] = 0ULL;

    float4 wv, xv0, xv1;
    {
        if (kqA < EE) wv = *(const float4*)(Wih + (size_t)(m0 + lmA) * EE + kqA);
        else { wv.x = wv.y = wv.z = wv.w = 0.0f; }
        xv0 = *(const float4*)(g_X + (size_t)(n0 + tok) * EP + f4b * 4);
        xv1 = *(const float4*)(g_X + (size_t)(n0 + tok) * EP + f4b * 4 + 4);
    }
    As[0][kqA + 0][lmA] = pack2(wv.x, wv.x);
    As[0][kqA + 1][lmA] = pack2(wv.y, wv.y);
    As[0][kqA + 2][lmA] = pack2(wv.z, wv.z);
    As[0][kqA + 3][lmA] = pack2(wv.w, wv.w);
    Xs[0][f4b * 4 + 0][tok] = xv0.x; Xs[0][f4b * 4 + 1][tok] = xv0.y;
    Xs[0][f4b * 4 + 2][tok] = xv0.z; Xs[0][f4b * 4 + 3][tok] = xv0.w;
    Xs[0][f4b * 4 + 4][tok] = xv1.x; Xs[0][f4b * 4 + 5][tok] = xv1.y;
    Xs[0][f4b * 4 + 6][tok] = xv1.z; Xs[0][f4b * 4 + 7][tok] = xv1.w;
    __syncthreads();

    const int NTILE = EP / 16;
    for (int i = 0; i < NTILE; i++) {
        int cb = i & 1, nb = (i + 1) & 1;
        if (i + 1 < NTILE) {
            int e0 = (i + 1) * 16;
            if (e0 + kqA < EE) wv = *(const float4*)(Wih + (size_t)(m0 + lmA) * EE + e0 + kqA);
            else { wv.x = wv.y = wv.z = wv.w = 0.0f; }
            xv0 = *(const float4*)(g_X + (size_t)(n0 + tok) * EP + e0 + f4b * 4);
            xv1 = *(const float4*)(g_X + (size_t)(n0 + tok) * EP + e0 + f4b * 4 + 4);
        }
#pragma unroll
        for (int k = 0; k < 16; k++) {
            ulonglong2 wA = *(const ulonglong2*)&As[cb][k][ty * 2];
            ulonglong2 wB = *(const ulonglong2*)&As[cb][k][32 + ty * 2];
            ulonglong2 xA = *(const ulonglong2*)&Xs[cb][k][tx * 4];
            ulonglong2 xB = *(const ulonglong2*)&Xs[cb][k][64 + tx * 4];
            acc[0][0] = fma2(wA.x, xA.x, acc[0][0]); acc[0][1] = fma2(wA.x, xA.y, acc[0][1]);
            acc[0][2] = fma2(wA.x, xB.x, acc[0][2]); acc[0][3] = fma2(wA.x, xB.y, acc[0][3]);
            acc[1][0] = fma2(wA.y, xA.x, acc[1][0]); acc[1][1] = fma2(wA.y, xA.y, acc[1][1]);
            acc[1][2] = fma2(wA.y, xB.x, acc[1][2]); acc[1][3] = fma2(wA.y, xB.y, acc[1][3]);
            acc[2][0] = fma2(wB.x, xA.x, acc[2][0]); acc[2][1] = fma2(wB.x, xA.y, acc[2][1]);
            acc[2][2] = fma2(wB.x, xB.x, acc[2][2]); acc[2][3] = fma2(wB.x, xB.y, acc[2][3]);
            acc[3][0] = fma2(wB.y, xA.x, acc[3][0]); acc[3][1] = fma2(wB.y, xA.y, acc[3][1]);
            acc[3][2] = fma2(wB.y, xB.x, acc[3][2]); acc[3][3] = fma2(wB.y, xB.y, acc[3][3]);
        }
        if (i + 1 < NTILE) {
            As[nb][kqA + 0][lmA] = pack2(wv.x, wv.x);
            As[nb][kqA + 1][lmA] = pack2(wv.y, wv.y);
            As[nb][kqA + 2][lmA] = pack2(wv.z, wv.z);
            As[nb][kqA + 3][lmA] = pack2(wv.w, wv.w);
            Xs[nb][f4b * 4 + 0][tok] = xv0.x; Xs[nb][f4b * 4 + 1][tok] = xv0.y;
            Xs[nb][f4b * 4 + 2][tok] = xv0.z; Xs[nb][f4b * 4 + 3][tok] = xv0.w;
            Xs[nb][f4b * 4 + 4][tok] = xv1.x; Xs[nb][f4b * 4 + 5][tok] = xv1.y;
            Xs[nb][f4b * 4 + 6][tok] = xv1.z; Xs[nb][f4b * 4 + 7][tok] = xv1.w;
        }
        __syncthreads();
    }

    int rows[4] = {m0 + ty * 2, m0 + ty * 2 + 1, m0 + 32 + ty * 2, m0 + 33 + ty * 2};
#pragma unroll
    for (int i = 0; i < 4; i++) {
        int row = rows[i];
        float bias = bih[row] + bhh[row];
#pragma unroll
        for (int c = 0; c < 4; c++) {
            float2 f = *(float2*)&acc[i][c];
            int n = n0 + (c < 2 ? tx * 4 + c * 2 : 64 + tx * 4 + (c - 2) * 2);
            int tt = n >> 5, bb2 = n & 31;
            float2 o;
            o.x = f.x + bias; o.y = f.y + bias;
            *(float2*)&g_xg[(((size_t)d * SS + tt) * T4H + row) * BB + bb2] = o;
        }
    }
}

// ---------------- persistent BiLSTM recurrence (round-5 verbatim: best measured) ----------------
__global__ __launch_bounds__(128, 1) void lstm_kernel(
    const float* __restrict__ WhhF, const float* __restrict__ WhhB) {
    extern __shared__ ull sm8[];
    ull*   W_dup = sm8;
    float* h_s   = (float*)(sm8 + 4096);
    ull*   part  = sm8 + 8192;

    int tid = threadIdx.x, bid = blockIdx.x;
    int d = bid >> 6, m = bid & 63;
    const float* Whh = d ? WhhB : WhhF;

    for (int i = tid; i < 4096; i += 128) {
        int r = i & 15, k = i >> 4;
        int gg = r >> 2, uu = r & 3;
        float w = Whh[(size_t)(gg * HH + m * 4 + uu) * HH + k];
        W_dup[k * 16 + r] = pack2(w, w);
    }
    __syncthreads();

    int lane = tid & 31, w = tid >> 5;
    int ggl = lane & 3, bg = lane >> 2;
    const ulonglong2* Wd2 = (const ulonglong2*)W_dup;
    const ulonglong2* H2  = (const ulonglong2*)h_s;
    int u = tid >> 5, b = tid & 31;
    float c_reg = 0.0f;
    unsigned* barD = g_bar + d * SS * 4;
    int mygrp = m >> 4;

    for (int it = 0; it < SS; it++) {
        int t = d ? (SS - 1 - it) : it;

        float xgv[4];
        const float* xgb = g_xg + ((size_t)(d * SS + t) * T4H) * BB;
#pragma unroll
        for (int gg = 0; gg < 4; gg++)
            xgv[gg] = xgb[(size_t)(gg * HH + m * 4 + u) * BB + b];

        if (it > 0) {
            unsigned* cp = barD + (it - 1) * 4 + w;
            unsigned v;
            do {
                asm volatile("ld.acquire.gpu.global.u32 %0, [%1];" : "=r"(v) : "l"(cp) : "memory");
            } while (v < 16u);

            int tp = d ? t + 1 : t - 1;
            const float4* src4 = (const float4*)(g_h + (size_t)(d * SS + tp) * HH * BB);
            float4* dst4 = (float4*)h_s;
#pragma unroll
            for (int j = 0; j < 16; j++) {
                int idx = w * 512 + lane + j * 32;
                dst4[idx] = src4[idx];
            }
            __syncwarp();

            ull a[4][2];
#pragma unroll
            for (int i = 0; i < 4; i++) { a[i][0] = 0ULL; a[i][1] = 0ULL; }
            int k0 = w * 64;
#pragma unroll 8
            for (int k = k0; k < k0 + 64; k++) {
                ulonglong2 w01 = Wd2[k * 8 + ggl * 2];
                ulonglong2 w23 = Wd2[k * 8 + ggl * 2 + 1];
                ulonglong2 hh  = H2[k * 8 + bg];
                a[0][0] = fma2(w01.x, hh.x, a[0][0]); a[0][1] = fma2(w01.x, hh.y, a[0][1]);
                a[1][0] = fma2(w01.y, hh.x, a[1][0]); a[1][1] = fma2(w01.y, hh.y, a[1][1]);
                a[2][0] = fma2(w23.x, hh.x, a[2][0]); a[2][1] = fma2(w23.x, hh.y, a[2][1]);
                a[3][0] = fma2(w23.y, hh.x, a[3][0]); a[3][1] = fma2(w23.y, hh.y, a[3][1]);
            }
#pragma unroll
            for (int i = 0; i < 4; i++) {
                ull* pr = part + (size_t)(w * 16 + ggl * 4 + i) * 17 + bg * 2;
                pr[0] = a[i][0]; pr[1] = a[i][1];
            }
        }
        __syncthreads();

        {
            const float* pf = (const float*)part;
            float g[4];
#pragma unroll
            for (int gg = 0; gg < 4; gg++) {
                float s = xgv[gg];
                if (it > 0) {
                    int r = gg * 4 + u;
#pragma unroll
                    for (int wi = 0; wi < 4; wi++)
                        s += pf[(((size_t)wi * 16 + r) * 17 + (b >> 1)) * 2 + (b & 1)];
                }
                g[gg] = s;
            }
            float iv = fsigmoid(g[0]);
            float fv = fsigmoid(g[1]);
            float gv = ftanh_fast(g[2]);
            float ov = fsigmoid(g[3]);
            c_reg = fv * c_reg + iv * gv;
            g_h[((size_t)(d * SS + t) * HH + m * 4 + u) * BB + b] = ov * ftanh_fast(c_reg);
        }
        __syncthreads();

        if (tid == 0) {
            unsigned* ap = barD + it * 4 + mygrp;
            asm volatile("red.release.gpu.global.add.u32 [%0], %1;" :: "l"(ap), "r"(1u) : "memory");
        }
    }
}

// ---------------- logits: 2 timesteps per block (halves Wtag staging traffic) ----------------
__global__ __launch_bounds__(256) void logits_kernel(const float* __restrict__ Wtag,
                                                     const float* __restrict__ btag) {
    extern __shared__ float hb[];          // [2 tt][512 k][32 b] = 128KB? no: 2*512*32*4 = 131072 too big
    // layout: hb[tt][k][b] for tt in {0,1}: 2*512*32 floats = 128KB exceeds smem.
    // Instead: stage wt once (38KB) + one h tile (64KB) at a time, loop tt.
    float* wt = hb;                        // [19][512]   (38KB)
    float* ht = hb + 19 * 512;             // [512][32]   (64KB)
    int t0 = blockIdx.x * 2;
    int tid = threadIdx.x;
    {
        const float4* ws = (const float4*)Wtag;
        float4* wd = (float4*)wt;
        for (int i = tid; i < 2432; i += 256) wd[i] = ws[i];
    }
    for (int tt = 0; tt < 2; tt++) {
        int t = t0 + tt;
        __syncthreads();   // wt ready (first iter) / previous ht reads done (second iter)
        for (int dd = 0; dd < 2; dd++) {
            const float4* src = (const float4*)(g_h + (size_t)(dd * SS + t) * HH * BB);
            float4* dst = (float4*)(ht + (size_t)dd * HH * BB);
            for (int i = tid; i < 2048; i += 256) dst[i] = src[i];
        }
        __syncthreads();
        for (int o = tid; o < BB * NT; o += 256) {
            int tag = o >> 5;              // warp-uniform -> wt reads broadcast
            int b = o & 31;
            float acc = btag[tag];
            const float* wr = wt + tag * 512;
#pragma unroll 8
            for (int k = 0; k < 2 * HH; k++) acc += ht[k * BB + b] * wr[k];
            g_logits[((size_t)b * SS + t) * NT + tag] = acc;
        }
    }
}

// ---------------- merged CRF forward + Viterbi, smem-staged, exp-hoisted ----------------
__global__ void crf_vit_kernel(const int* __restrict__ mask, const int* __restrict__ labels,
                               const float* __restrict__ trans, float* __restrict__ out) {
    extern __shared__ float smc[];
    float* tr  = smc;
    float* lg  = smc + 364;
    int*   msk = (int*)(smc + 364 + 4864);
    int*   lbl = msk + 256;
    int*   ptr_s = msk + 512;
    __shared__ float st[NT];
    __shared__ float p[NT];

    int b = blockIdx.x, j = threadIdx.x;
    for (int i = j; i < NT * NT; i += 32) tr[i] = trans[i];
    {
        const float4* src = (const float4*)(g_logits + (size_t)b * SS * NT);
        float4* dst = (float4*)lg;
        for (int i = j; i < SS * NT / 4; i += 32) dst[i] = src[i];
    }
    for (int i = j; i < SS; i += 32) {
        msk[i] = mask[b * SS + i];
        lbl[i] = labels[b * SS + i];
    }
    __syncthreads();

    if (blockIdx.y == 0) {
        float Ecol[NT];
        if (j < NT) {
#pragma unroll
            for (int i = 0; i < NT; i++) Ecol[i] = __expf(tr[i * NT + j]);
            st[j] = lg[j] + tr[TSTART * NT + j];
        }
        __syncthreads();
        for (int t = 1; t < SS; t++) {
            int mt = msk[t];
            float mx = -1e30f, nv = 0.0f;
            if (j < NT) {
#pragma unroll
                for (int i = 0; i < NT; i++) mx = fmaxf(mx, st[i]);
                p[j] = __expf(st[j] - mx);
            }
            __syncthreads();
            if (j < NT) {
                float s = 0.0f;
#pragma unroll
                for (int i = 0; i < NT; i++) s += p[i] * Ecol[i];
                nv = mx + __logf(s) + lg[t * NT + j];
            }
            __syncthreads();
            if (j < NT && mt > 0) st[j] = nv;
            __syncthreads();
        }
        if (j == 0) {
            float mx = -1e30f;
            for (int i = 0; i < NT; i++) mx = fmaxf(mx, st[i] + tr[i * NT + TSTOP]);
            float sum = 0.0f;
            for (int i = 0; i < NT; i++) sum += __expf(st[i] + tr[i * NT + TSTOP] - mx);
            float logZ = mx + __logf(sum);
            float gold = 0.0f;
            int prev = TSTART, len = 0;
            for (int t = 0; t < SS; t++) {
                int lab = lbl[t];
                if (msk[t] > 0) {
                    gold += tr[prev * NT + lab] + lg[t * NT + lab];
                    len++;
                }
                prev = lab;
            }
            int last = lbl[len - 1];
            gold += tr[last * NT + TSTOP];
            atomicAdd(out, (logZ - gold) * (1.0f / (float)BB));
        }
    } else {
        float Tcol[NT];
        if (j < NT) {
#pragma unroll
            for (int i = 0; i < NT; i++) Tcol[i] = tr[i * NT + j];
            st[j] = lg[j] + tr[TSTART * NT + j];
        }
        __syncthreads();
        for (int t = 1; t < SS; t++) {
            int mt = msk[t];
            float nv = 0.0f;
            int arg = j;
            if (j < NT) {
                float best = -1e30f;
                int bi = 0;
#pragma unroll
                for (int i = 0; i < NT; i++) {
                    float v = st[i] + Tcol[i];
                    if (v > best) { best = v; bi = i; }  // strict '>' => first max (jnp.argmax)
                }
                nv = best + lg[t * NT + j];
                if (mt > 0) arg = bi;
            }
            __syncthreads();
            if (j < NT) {
                if (mt > 0) st[j] = nv;
                ptr_s[t * NT + j] = arg;
            }
            __syncthreads();
        }
        if (j == 0) {
            float best = -1e30f;
            int bl = 0;
            for (int i = 0; i < NT; i++) {
                float v = st[i] + tr[i * NT + TSTOP];
                if (v > best) { best = v; bl = i; }
            }
            int tag = bl;
            for (int t = SS - 1; t >= 1; t--) {
                out[1 + b * SS + t] = (float)(msk[t] > 0 ? tag : 0);
                tag = ptr_s[t * NT + tag];
            }
            out[1 + b * SS + 0] = (float)(msk[0] > 0 ? tag : 0);
        }
    }
}

extern "C" void kernel_launch(void* const* d_in, const int* in_sizes, int n_in,
                              void* d_out, int out_size) {
    int o = (in_sizes[4] == 1) ? 0 : -1;
    const int*   word   = (const int*)d_in[0];
    const int*   mask   = (const int*)d_in[1];
    const int*   labels = (const int*)d_in[2];
    const float* emb    = (const float*)d_in[5 + o];
    const float* WihF   = (const float*)d_in[6 + o];
    const float* WhhF   = (const float*)d_in[7 + o];
    const float* bihF   = (const float*)d_in[8 + o];
    const float* bhhF   = (const float*)d_in[9 + o];
    const float* WihB   = (const float*)d_in[10 + o];
    const float* WhhB   = (const float*)d_in[11 + o];
    const float* bihB   = (const float*)d_in[12 + o];
    const float* bhhB   = (const float*)d_in[13 + o];
    const float* Wtag   = (const float*)d_in[14 + o];
    const float* btag   = (const float*)d_in[15 + o];
    const float* trans  = (const float*)d_in[16 + o];
    float* out = (float*)d_out;

    const int lstm_smem = (4096 + 4096 + 1088) * 8;           // 74240 B
    const int logits_smem = (19 * 512 + 512 * 32) * 4;        // 104448 B
    const int crf_smem = (364 + 4864 + 256 + 256 + 4864) * 4; // 42416 B
    cudaFuncSetAttribute(lstm_kernel, cudaFuncAttributeMaxDynamicSharedMemorySize, lstm_smem);
    cudaFuncSetAttribute(logits_kernel, cudaFuncAttributeMaxDynamicSharedMemorySize, logits_smem);

    embed_kernel<<<(BB * SS * (EP / 4) + 255) / 256, 256>>>(word, mask, emb, out);
    {
        dim3 grid(BB * SS / 128, T4H / 64, 2);
        gemm_xg_kernel<<<grid, 256>>>(WihF, WihB, bihF, bhhF, bihB, bhhB);
    }
    lstm_kernel<<<128, 128, lstm_smem>>>(WhhF, WhhB);
    logits_kernel<<<SS / 2, 256, logits_smem>>>(Wtag, btag);
    crf_vit_kernel<<<dim3(BB, 2), 32, crf_smem>>>(mask, labels, trans, out);
}